// round 1
// baseline (speedup 1.0000x reference)
#include <cuda_runtime.h>

// ANFIS_61280593380167 — B=8192, D=256, R=64, O=256, fp32.
//
// out[b,o] = sum_r f[b,r] * (x[b,:] @ W[r] + b[r])
// f[b,r]   = frs[b,r] / (sum_r frs[b,r] + 1e-8)
// frs[b,r] = exp( sum_i -(x[b,i]-mu[i,r])^2 / (2 sig[i,r]^2) )
//
// Key structural fact: when f[b,r] == 0.0f exactly (fp32 exp underflow, which
// the reference also produces), the row's contribution is exactly zero.
// Kernel 2 therefore fast-paths rows whose entire f-row is zero (exact-zero
// write) and runs a faithful fp32 per-rule mixture otherwise. Correct for any
// input; fast when memberships underflow.

#define B_SZ 8192
#define D_SZ 256
#define R_SZ 64
#define O_SZ 256

// Scratch for f[b,r] (allocation-free rule: __device__ global array).
__device__ float g_f[B_SZ * R_SZ];

// ---------------------------------------------------------------------------
// Kernel 1: memberships + normalization. 32 batch rows per 256-thread block.
// Thread layout: r = tid & 63 (rule), msub = tid >> 6 (row sub-group of 4),
// each thread accumulates 8 rows' logits for its rule, amortizing mu/sig loads.
// ---------------------------------------------------------------------------
__global__ __launch_bounds__(256) void memb_kernel(
    const float* __restrict__ x,
    const float* __restrict__ mu,
    const float* __restrict__ sig)
{
    __shared__ float xs[32][D_SZ];    // 32 KB
    __shared__ float es[32][R_SZ];    // 8 KB
    __shared__ float ssum[32];

    const int row0 = blockIdx.x * 32;
    const int tid  = threadIdx.x;

    // Stage x tile (32 rows x 256 cols, contiguous since D==256).
    #pragma unroll
    for (int k = 0; k < 32; k++) {
        int idx = tid + k * 256;               // idx = m*256 + i
        xs[idx >> 8][idx & 255] = x[row0 * D_SZ + idx];
    }
    __syncthreads();

    const int r    = tid & 63;
    const int msub = tid >> 6;                 // 0..3

    float acc[8];
    #pragma unroll
    for (int g = 0; g < 8; g++) acc[g] = 0.0f;

    for (int i = 0; i < D_SZ; i++) {
        float mv  = mu [i * R_SZ + r];
        float sv  = sig[i * R_SZ + r];
        float inv = 0.5f / (sv * sv);          // 1/(2 sig^2)
        #pragma unroll
        for (int g = 0; g < 8; g++) {
            float d = xs[msub * 8 + g][i] - mv;
            acc[g] = fmaf(-d * d, inv, acc[g]);
        }
    }

    #pragma unroll
    for (int g = 0; g < 8; g++) {
        es[msub * 8 + g][r] = expf(acc[g]);    // AMPLI == 0
    }
    __syncthreads();

    // Per-row sum over 64 rules.
    if (tid < 32) {
        float s = 0.0f;
        #pragma unroll
        for (int rr = 0; rr < R_SZ; rr++) s += es[tid][rr];
        ssum[tid] = s + 1e-8f;
    }
    __syncthreads();

    // Normalize and store f (coalesced over r).
    #pragma unroll
    for (int k = 0; k < 8; k++) {
        int idx = tid + k * 256;               // idx = m*64 + rr
        int m   = idx >> 6;
        g_f[(row0 + m) * R_SZ + (idx & 63)] = es[m][idx & 63] / ssum[m];
    }
}

// ---------------------------------------------------------------------------
// Kernel 2: output. One block (256 threads) per batch row; thread = output o.
// Fast path: entire f-row exactly zero -> out row is exactly zero.
// Slow path: out[b,o] = sum_{r: f_r != 0} f_r * (sum_i x_i W[r,i,o] + b[r,o]).
// ---------------------------------------------------------------------------
__global__ __launch_bounds__(256) void out_kernel(
    const float* __restrict__ x,
    const float* __restrict__ W,
    const float* __restrict__ bias,
    float* __restrict__ out)
{
    const int b   = blockIdx.x;
    const int tid = threadIdx.x;

    __shared__ float fs[R_SZ];
    __shared__ float xsh[D_SZ];

    float myf = 0.0f;
    if (tid < R_SZ) {
        myf = g_f[b * R_SZ + tid];
        fs[tid] = myf;
    }
    xsh[tid] = x[b * D_SZ + tid];

    int nz = __syncthreads_or(myf != 0.0f);

    float acc = 0.0f;
    if (nz) {
        for (int r = 0; r < R_SZ; r++) {
            float fr = fs[r];                  // uniform branch per block
            if (fr != 0.0f) {
                const float* Wp = W + (size_t)(r * D_SZ) * O_SZ + tid;
                float dot = 0.0f;
                #pragma unroll 8
                for (int i = 0; i < D_SZ; i++)
                    dot = fmaf(xsh[i], Wp[(size_t)i * O_SZ], dot);
                acc = fmaf(fr, dot + bias[r * O_SZ + tid], acc);
            }
        }
    }
    out[b * O_SZ + tid] = acc;
}

// ---------------------------------------------------------------------------
extern "C" void kernel_launch(void* const* d_in, const int* in_sizes, int n_in,
                              void* d_out, int out_size)
{
    const float* x   = (const float*)d_in[0];   // [8192, 256]
    const float* mu  = (const float*)d_in[1];   // [256, 64]
    const float* sig = (const float*)d_in[2];   // [256, 64]
    const float* W   = (const float*)d_in[3];   // [64, 256, 256]
    const float* b   = (const float*)d_in[4];   // [64, 256]
    float* out       = (float*)d_out;           // [8192, 256]

    memb_kernel<<<B_SZ / 32, 256>>>(x, mu, sig);
    out_kernel<<<B_SZ, 256>>>(x, W, b, out);
}

// round 2
// speedup vs baseline: 4.4487x; 4.4487x over previous
#include <cuda_runtime.h>

// ANFIS_61280593380167 — B=8192, D=256, R=64, O=256, fp32.
//
// out[b,o] = sum_r f[b,r] * (x[b,:] @ W[r] + b[r])
// f[b,r]   = frs[b,r] / (sum_r frs[b,r] + 1e-8),  frs = exp(-sum (x-mu)^2/(2 sig^2))
//
// Logits are ~ -128 for this data, so frs underflows to exact fp32 zero for ~99%
// of (b,r) pairs — just like the reference. Zero f contributes exactly zero.
// Strategy: compute f, compact the nonzero (b, f) pairs into per-rule lists,
// then process only those pairs with rule-major W reuse. Correct for any input
// (falls back to the full mixture if everything is nonzero), fast when sparse.

#define B_SZ 8192
#define D_SZ 256
#define R_SZ 64
#define O_SZ 256
#define MCH  16      // batch rows per expert chunk
#define XPAD 20      // padded row stride (floats) for transposed x tile
#define CHUNKS_PER_R 8

// Scratch (__device__ globals: allocation-free rule)
__device__ int   g_count[R_SZ];
__device__ int   g_lb[R_SZ][B_SZ];
__device__ float g_lf[R_SZ][B_SZ];
__device__ float g_a [D_SZ * R_SZ];   // 1/(2 sig^2)
__device__ float g_b2[D_SZ * R_SZ];   // 2 mu / (2 sig^2)
__device__ float g_c [R_SZ];          // sum_i mu^2/(2 sig^2)

// ---------------------------------------------------------------------------
// Zero output + rule counters.
// ---------------------------------------------------------------------------
__global__ __launch_bounds__(256) void reset_kernel(float4* __restrict__ out4)
{
    const int idx = blockIdx.x * 256 + threadIdx.x;   // 512*256 = 131072 threads
    const float4 z = make_float4(0.f, 0.f, 0.f, 0.f);
    #pragma unroll
    for (int k = 0; k < 4; k++)
        out4[idx + k * 131072] = z;                   // 524288 float4 total
    if (blockIdx.x == 0 && threadIdx.x < R_SZ)
        g_count[threadIdx.x] = 0;
}

// ---------------------------------------------------------------------------
// Precompute expanded-quadratic coefficients. grid=64 (r), block=256 (i).
// ---------------------------------------------------------------------------
__global__ __launch_bounds__(256) void prep_kernel(
    const float* __restrict__ mu, const float* __restrict__ sig)
{
    const int r = blockIdx.x, i = threadIdx.x;
    const float m = mu [i * R_SZ + r];
    const float s = sig[i * R_SZ + r];
    const float a = 0.5f / (s * s);
    g_a [i * R_SZ + r] = a;
    g_b2[i * R_SZ + r] = 2.0f * m * a;

    __shared__ float red[256];
    red[i] = m * m * a;
    __syncthreads();
    #pragma unroll
    for (int st = 128; st > 0; st >>= 1) {
        if (i < st) red[i] += red[i + st];
        __syncthreads();
    }
    if (i == 0) g_c[r] = red[0];
}

// ---------------------------------------------------------------------------
// Memberships + normalization + compaction. 32 batch rows / 256-thread block.
// logit[b,r] = sum_i x * fma(x, -a, b2)  -  c[r]
// ---------------------------------------------------------------------------
__global__ __launch_bounds__(256) void memb_kernel(const float* __restrict__ x)
{
    __shared__ float xs[32][D_SZ];    // 32 KB
    __shared__ float es[32][R_SZ];    // 8 KB
    __shared__ float ssum[32];

    const int row0 = blockIdx.x * 32;
    const int tid  = threadIdx.x;

    #pragma unroll
    for (int k = 0; k < 32; k++) {
        int idx = tid + k * 256;
        xs[idx >> 8][idx & 255] = x[row0 * D_SZ + idx];
    }
    __syncthreads();

    const int r    = tid & 63;
    const int msub = tid >> 6;        // 0..3 -> rows msub*8 .. msub*8+7

    float acc[8];
    #pragma unroll
    for (int g = 0; g < 8; g++) acc[g] = 0.0f;

    for (int i = 0; i < D_SZ; i++) {
        const float av = g_a [i * R_SZ + r];
        const float bv = g_b2[i * R_SZ + r];
        #pragma unroll
        for (int g = 0; g < 8; g++) {
            const float xv = xs[msub * 8 + g][i];
            acc[g] = fmaf(xv, fmaf(xv, -av, bv), acc[g]);
        }
    }

    const float cv = g_c[r];
    #pragma unroll
    for (int g = 0; g < 8; g++)
        es[msub * 8 + g][r] = expf(acc[g] - cv);
    __syncthreads();

    if (tid < 32) {
        float s = 0.0f;
        #pragma unroll
        for (int rr = 0; rr < R_SZ; rr++) s += es[tid][rr];
        ssum[tid] = s + 1e-8f;
    }
    __syncthreads();

    #pragma unroll
    for (int k = 0; k < 8; k++) {
        int idx = tid + k * 256;      // idx = m*64 + rr
        int m   = idx >> 6;
        int rr  = idx & 63;
        float f = es[m][rr] / ssum[m];
        if (f != 0.0f) {
            int pos = atomicAdd(&g_count[rr], 1);
            g_lb[rr][pos] = row0 + m;
            g_lf[rr][pos] = f;
        }
    }
}

// ---------------------------------------------------------------------------
// Expert mixture over compacted pairs. 8 blocks per rule, 16 rows per chunk.
// Thread = output column o. W row reused across 16 register accumulators.
// ---------------------------------------------------------------------------
__global__ __launch_bounds__(256) void expert_kernel(
    const float* __restrict__ x,
    const float* __restrict__ W,
    const float* __restrict__ bias,
    float* __restrict__ out)
{
    const int r   = blockIdx.x >> 3;            // 0..63
    const int sub = blockIdx.x & 7;             // 0..7
    const int tid = threadIdx.x;
    const int cnt = g_count[r];
    if (cnt == 0) return;

    __shared__ float xs_t[D_SZ * XPAD];         // x transposed: [i][m], pad 20
    __shared__ int   sb[MCH];
    __shared__ float sf[MCH];

    const float  bv = bias[r * O_SZ + tid];
    const float* Wp = W + ((size_t)r << 16) + tid;

    for (int c0 = sub * MCH; c0 < cnt; c0 += CHUNKS_PER_R * MCH) {
        __syncthreads();                        // protect sb/sf/xs_t reuse
        if (tid < MCH) {
            int p = c0 + tid;
            int bb = 0; float ff = 0.0f;
            if (p < cnt) { bb = g_lb[r][p]; ff = g_lf[r][p]; }
            sb[tid] = bb; sf[tid] = ff;
        }
        __syncthreads();

        // Stage 16 x-rows transposed (coalesced LDG per row).
        #pragma unroll
        for (int m = 0; m < MCH; m++)
            xs_t[tid * XPAD + m] = x[(size_t)sb[m] * D_SZ + tid];
        __syncthreads();

        float acc[MCH];
        #pragma unroll
        for (int m = 0; m < MCH; m++) acc[m] = 0.0f;

        #pragma unroll 4
        for (int i = 0; i < D_SZ; i++) {
            const float w = Wp[i << 8];                 // W[r][i][o], L1/L2 hit
            const float* xp = &xs_t[i * XPAD];
            #pragma unroll
            for (int m = 0; m < MCH; m++)
                acc[m] = fmaf(w, xp[m], acc[m]);
        }

        #pragma unroll
        for (int m = 0; m < MCH; m++) {
            const float f = sf[m];
            if (f != 0.0f)
                atomicAdd(&out[(size_t)sb[m] * O_SZ + tid], f * (acc[m] + bv));
        }
    }
}

// ---------------------------------------------------------------------------
extern "C" void kernel_launch(void* const* d_in, const int* in_sizes, int n_in,
                              void* d_out, int out_size)
{
    const float* x   = (const float*)d_in[0];   // [8192, 256]
    const float* mu  = (const float*)d_in[1];   // [256, 64]
    const float* sig = (const float*)d_in[2];   // [256, 64]
    const float* W   = (const float*)d_in[3];   // [64, 256, 256]
    const float* b   = (const float*)d_in[4];   // [64, 256]
    float* out       = (float*)d_out;           // [8192, 256]

    reset_kernel<<<512, 256>>>((float4*)out);
    prep_kernel<<<R_SZ, 256>>>(mu, sig);
    memb_kernel<<<B_SZ / 32, 256>>>(x);
    expert_kernel<<<R_SZ * CHUNKS_PER_R, 256>>>(x, W, b, out);
}

// round 4
// speedup vs baseline: 5.0826x; 1.1425x over previous
#include <cuda_runtime.h>

// ANFIS_61280593380167 — B=8192, D=256, R=64, O=256, fp32.
//
// out[b,o] = sum_r f[b,r] * (x[b,:] @ W[r] + b[r])
// f[b,r]   = frs[b,r] / (sum_r frs[b,r] + 1e-8),  frs = exp(-sum (x-mu)^2/(2 sig^2))
//
// frs underflows to exact fp32 zero for ~99% of (b,r) pairs (as in the
// reference); zero f contributes exactly zero. Strategy: compute f, compact
// nonzero (b, f) pairs into per-rule lists, process only those with rule-major
// W reuse. Correct for any input; fast when sparse.

#define B_SZ 8192
#define D_SZ 256
#define R_SZ 64
#define O_SZ 256
#define MCH  16      // batch rows per expert chunk
#define XPAD 20      // padded row stride (floats); 80B keeps float4 alignment
#define CHUNKS_PER_R 16
#define IUNR 16      // W prefetch depth

// Scratch (__device__ globals: allocation-free rule)
__device__ int   g_count[R_SZ];
__device__ int   g_lb[R_SZ][B_SZ];
__device__ float g_lf[R_SZ][B_SZ];
__device__ float g_a [D_SZ * R_SZ];   // 1/(2 sig^2)
__device__ float g_b2[D_SZ * R_SZ];   // 2 mu / (2 sig^2)
__device__ float g_c [R_SZ];          // sum_i mu^2/(2 sig^2)

// ---------------------------------------------------------------------------
__global__ __launch_bounds__(256) void reset_kernel(float4* __restrict__ out4)
{
    const int idx = blockIdx.x * 256 + threadIdx.x;
    const float4 z = make_float4(0.f, 0.f, 0.f, 0.f);
    #pragma unroll
    for (int k = 0; k < 4; k++)
        out4[idx + k * 131072] = z;
    if (blockIdx.x == 0 && threadIdx.x < R_SZ)
        g_count[threadIdx.x] = 0;
}

// ---------------------------------------------------------------------------
__global__ __launch_bounds__(256) void prep_kernel(
    const float* __restrict__ mu, const float* __restrict__ sig)
{
    const int r = blockIdx.x, i = threadIdx.x;
    const float m = mu [i * R_SZ + r];
    const float s = sig[i * R_SZ + r];
    const float a = 0.5f / (s * s);
    g_a [i * R_SZ + r] = a;
    g_b2[i * R_SZ + r] = 2.0f * m * a;

    __shared__ float red[256];
    red[i] = m * m * a;
    __syncthreads();
    #pragma unroll
    for (int st = 128; st > 0; st >>= 1) {
        if (i < st) red[i] += red[i + st];
        __syncthreads();
    }
    if (i == 0) g_c[r] = red[0];
}

// ---------------------------------------------------------------------------
// Memberships + normalization + compaction. 32 batch rows / 256-thread block.
// logit[b,r] = sum_i x * fma(x, -a, b2)  -  c[r]
// ---------------------------------------------------------------------------
__global__ __launch_bounds__(256) void memb_kernel(const float* __restrict__ x)
{
    __shared__ float xs[32][D_SZ];
    __shared__ float es[32][R_SZ];
    __shared__ float ssum[32];

    const int row0 = blockIdx.x * 32;
    const int tid  = threadIdx.x;

    #pragma unroll
    for (int k = 0; k < 32; k++) {
        int idx = tid + k * 256;
        xs[idx >> 8][idx & 255] = x[row0 * D_SZ + idx];
    }
    __syncthreads();

    const int r    = tid & 63;
    const int msub = tid >> 6;

    float acc[8];
    #pragma unroll
    for (int g = 0; g < 8; g++) acc[g] = 0.0f;

    #pragma unroll 4
    for (int i = 0; i < D_SZ; i++) {
        const float av = g_a [i * R_SZ + r];
        const float bv = g_b2[i * R_SZ + r];
        #pragma unroll
        for (int g = 0; g < 8; g++) {
            const float xv = xs[msub * 8 + g][i];
            acc[g] = fmaf(xv, fmaf(xv, -av, bv), acc[g]);
        }
    }

    const float cv = g_c[r];
    #pragma unroll
    for (int g = 0; g < 8; g++)
        es[msub * 8 + g][r] = expf(acc[g] - cv);
    __syncthreads();

    if (tid < 32) {
        float s = 0.0f;
        #pragma unroll
        for (int rr = 0; rr < R_SZ; rr++) s += es[tid][rr];
        ssum[tid] = s + 1e-8f;
    }
    __syncthreads();

    #pragma unroll
    for (int k = 0; k < 8; k++) {
        int idx = tid + k * 256;      // idx = m*64 + rr
        int m   = idx >> 6;
        int rr  = idx & 63;
        float f = es[m][rr] / ssum[m];
        if (f != 0.0f) {
            int pos = atomicAdd(&g_count[rr], 1);
            g_lb[rr][pos] = row0 + m;
            g_lf[rr][pos] = f;
        }
    }
}

// ---------------------------------------------------------------------------
// Expert mixture over compacted pairs. 16 blocks per rule, 16 rows per chunk.
// Thread = output column o. W prefetched 16-deep (software pipeline) so LDG
// latency overlaps the 256 FMAs of the previous group.
// ---------------------------------------------------------------------------
__global__ __launch_bounds__(256) void expert_kernel(
    const float* __restrict__ x,
    const float* __restrict__ W,
    const float* __restrict__ bias,
    float* __restrict__ out)
{
    const int r   = blockIdx.x >> 4;            // 0..63
    const int sub = blockIdx.x & 15;            // 0..15
    const int tid = threadIdx.x;
    const int cnt = g_count[r];
    if (sub * MCH >= cnt) return;

    __shared__ float xs_t[D_SZ * XPAD];         // x transposed: [i][m]
    __shared__ int   sb[MCH];
    __shared__ float sf[MCH];

    const float  bv = bias[r * O_SZ + tid];
    const float* Wp = W + ((size_t)r << 16) + tid;

    for (int c0 = sub * MCH; c0 < cnt; c0 += CHUNKS_PER_R * MCH) {
        __syncthreads();
        if (tid < MCH) {
            int p = c0 + tid;
            int bb = 0; float ff = 0.0f;
            if (p < cnt) { bb = g_lb[r][p]; ff = g_lf[r][p]; }
            sb[tid] = bb; sf[tid] = ff;
        }
        __syncthreads();

        #pragma unroll
        for (int m = 0; m < MCH; m++)
            xs_t[tid * XPAD + m] = x[(size_t)sb[m] * D_SZ + tid];
        __syncthreads();

        float acc[MCH];
        #pragma unroll
        for (int m = 0; m < MCH; m++) acc[m] = 0.0f;

        // Software-pipelined over i in groups of IUNR: prefetch next group's
        // W values while FMA-ing the current group's.
        float w[IUNR];
        #pragma unroll
        for (int k = 0; k < IUNR; k++) w[k] = Wp[k << 8];

        for (int i0 = 0; i0 < D_SZ; i0 += IUNR) {
            float wn[IUNR];
            const bool more = (i0 + IUNR) < D_SZ;
            #pragma unroll
            for (int k = 0; k < IUNR; k++)
                if (more) wn[k] = Wp[(i0 + IUNR + k) << 8];

            #pragma unroll
            for (int k = 0; k < IUNR; k++) {
                const float4* xp = (const float4*)&xs_t[(i0 + k) * XPAD];
                const float4 x0 = xp[0], x1 = xp[1], x2 = xp[2], x3 = xp[3];
                const float wk = w[k];
                acc[0]  = fmaf(wk, x0.x, acc[0]);
                acc[1]  = fmaf(wk, x0.y, acc[1]);
                acc[2]  = fmaf(wk, x0.z, acc[2]);
                acc[3]  = fmaf(wk, x0.w, acc[3]);
                acc[4]  = fmaf(wk, x1.x, acc[4]);
                acc[5]  = fmaf(wk, x1.y, acc[5]);
                acc[6]  = fmaf(wk, x1.z, acc[6]);
                acc[7]  = fmaf(wk, x1.w, acc[7]);
                acc[8]  = fmaf(wk, x2.x, acc[8]);
                acc[9]  = fmaf(wk, x2.y, acc[9]);
                acc[10] = fmaf(wk, x2.z, acc[10]);
                acc[11] = fmaf(wk, x2.w, acc[11]);
                acc[12] = fmaf(wk, x3.x, acc[12]);
                acc[13] = fmaf(wk, x3.y, acc[13]);
                acc[14] = fmaf(wk, x3.z, acc[14]);
                acc[15] = fmaf(wk, x3.w, acc[15]);
            }
            #pragma unroll
            for (int k = 0; k < IUNR; k++) w[k] = wn[k];
        }

        #pragma unroll
        for (int m = 0; m < MCH; m++) {
            const float f = sf[m];
            if (f != 0.0f)
                atomicAdd(&out[(size_t)sb[m] * O_SZ + tid], f * (acc[m] + bv));
        }
    }
}

// ---------------------------------------------------------------------------
extern "C" void kernel_launch(void* const* d_in, const int* in_sizes, int n_in,
                              void* d_out, int out_size)
{
    const float* x   = (const float*)d_in[0];   // [8192, 256]
    const float* mu  = (const float*)d_in[1];   // [256, 64]
    const float* sig = (const float*)d_in[2];   // [256, 64]
    const float* W   = (const float*)d_in[3];   // [64, 256, 256]
    const float* b   = (const float*)d_in[4];   // [64, 256]
    float* out       = (float*)d_out;           // [8192, 256]

    reset_kernel<<<512, 256>>>((float4*)out);
    prep_kernel<<<R_SZ, 256>>>(mu, sig);
    memb_kernel<<<B_SZ / 32, 256>>>(x);
    expert_kernel<<<R_SZ * CHUNKS_PER_R, 256>>>(x, W, b, out);
}

// round 5
// speedup vs baseline: 6.2805x; 1.2357x over previous
#include <cuda_runtime.h>

// ANFIS_61280593380167 — B=8192, D=256, R=64, O=256, fp32.
//
// out[b,o] = sum_r f[b,r] * (x[b,:] @ W[r] + b[r])
// f[b,r]   = frs[b,r] / (sum_r frs[b,r] + 1e-8),  frs = exp(-sum (x-mu)^2/(2 sig^2))
//
// frs underflows to exact fp32 zero for ~99% of (b,r) pairs (as in the
// reference); zero f contributes exactly zero. Strategy: compute f, compact
// nonzero (b, f) pairs into per-rule lists, build a balanced chunk worklist,
// and process only real work with persistent blocks. Correct for any input
// (degenerates to the full dense mixture); fast when sparse.

#define B_SZ 8192
#define D_SZ 256
#define R_SZ 64
#define O_SZ 256
#define MCH   16     // batch rows per expert chunk
#define XPAD  20     // x-tile stride (floats) in expert (float4-aligned)
#define MROWS 32     // batch rows per memb block
#define MPAD  36     // x-tile stride (floats) in memb (float4-aligned)
#define IUNR  16     // W prefetch depth
#define EGRID 592    // persistent expert blocks (4 per SM x 148)

// Scratch (__device__ globals: allocation-free rule)
__device__ int    g_count[R_SZ];
__device__ int    g_lb[R_SZ][B_SZ];
__device__ float  g_lf[R_SZ][B_SZ];
__device__ float2 g_ab[D_SZ * R_SZ];  // {a = 1/(2 sig^2), b2 = 2 mu a}
__device__ float  g_c [R_SZ];         // sum_i mu^2 a
__device__ int    g_work[R_SZ * (B_SZ / MCH) * 2];
__device__ int    g_nwork;
__device__ int    g_fetch;

// ---------------------------------------------------------------------------
__global__ __launch_bounds__(256) void reset_kernel(float4* __restrict__ out4)
{
    const int idx = blockIdx.x * 256 + threadIdx.x;
    const float4 z = make_float4(0.f, 0.f, 0.f, 0.f);
    #pragma unroll
    for (int k = 0; k < 4; k++)
        out4[idx + k * 131072] = z;
    if (blockIdx.x == 0) {
        if (threadIdx.x < R_SZ) g_count[threadIdx.x] = 0;
        if (threadIdx.x == 0) { g_nwork = 0; g_fetch = 0; }
    }
}

// ---------------------------------------------------------------------------
// Expanded-quadratic coefficients: logit = sum_i x*fma(x,-a,b2) - c
// ---------------------------------------------------------------------------
__global__ __launch_bounds__(256) void prep_kernel(
    const float* __restrict__ mu, const float* __restrict__ sig)
{
    const int r = blockIdx.x, i = threadIdx.x;
    const float m = mu [i * R_SZ + r];
    const float s = sig[i * R_SZ + r];
    const float a = 0.5f / (s * s);
    g_ab[i * R_SZ + r] = make_float2(a, 2.0f * m * a);

    __shared__ float red[256];
    red[i] = m * m * a;
    __syncthreads();
    #pragma unroll
    for (int st = 128; st > 0; st >>= 1) {
        if (i < st) red[i] += red[i + st];
        __syncthreads();
    }
    if (i == 0) g_c[r] = red[0];
}

// ---------------------------------------------------------------------------
// Memberships + normalization + compaction. 32 rows / 256-thread block.
// x tile staged TRANSPOSED ([i][m]) so each thread grabs its 8 row-values
// with two broadcast LDS.128 per i. Coefficients: one LDG.64 per i.
// ---------------------------------------------------------------------------
__global__ __launch_bounds__(256) void memb_kernel(const float* __restrict__ x)
{
    __shared__ float xs_t[D_SZ * MPAD];        // 36 KB, [i][m]
    __shared__ float es[MROWS * 65];           // 8.3 KB, padded rows
    __shared__ float ssum[MROWS];

    const int row0 = blockIdx.x * MROWS;
    const int tid  = threadIdx.x;

    // Stage transposed: thread owns column i = tid for all 32 rows.
    #pragma unroll 8
    for (int m = 0; m < MROWS; m++)
        xs_t[tid * MPAD + m] = x[(size_t)(row0 + m) * D_SZ + tid];
    __syncthreads();

    const int r    = tid & 63;
    const int msub = tid >> 6;                 // rows msub*8 .. +7

    float acc[8];
    #pragma unroll
    for (int g = 0; g < 8; g++) acc[g] = 0.0f;

    #pragma unroll 4
    for (int i = 0; i < D_SZ; i++) {
        const float2 ab = g_ab[i * R_SZ + r];
        const float4* xp = (const float4*)&xs_t[i * MPAD + msub * 8];
        const float4 x0 = xp[0], x1 = xp[1];
        acc[0] = fmaf(x0.x, fmaf(x0.x, -ab.x, ab.y), acc[0]);
        acc[1] = fmaf(x0.y, fmaf(x0.y, -ab.x, ab.y), acc[1]);
        acc[2] = fmaf(x0.z, fmaf(x0.z, -ab.x, ab.y), acc[2]);
        acc[3] = fmaf(x0.w, fmaf(x0.w, -ab.x, ab.y), acc[3]);
        acc[4] = fmaf(x1.x, fmaf(x1.x, -ab.x, ab.y), acc[4]);
        acc[5] = fmaf(x1.y, fmaf(x1.y, -ab.x, ab.y), acc[5]);
        acc[6] = fmaf(x1.z, fmaf(x1.z, -ab.x, ab.y), acc[6]);
        acc[7] = fmaf(x1.w, fmaf(x1.w, -ab.x, ab.y), acc[7]);
    }

    const float cv = g_c[r];
    #pragma unroll
    for (int g = 0; g < 8; g++)
        es[(msub * 8 + g) * 65 + r] = expf(acc[g] - cv);
    __syncthreads();

    if (tid < MROWS) {
        float s = 0.0f;
        #pragma unroll
        for (int rr = 0; rr < R_SZ; rr++) s += es[tid * 65 + rr];
        ssum[tid] = s + 1e-8f;
    }
    __syncthreads();

    #pragma unroll
    for (int k = 0; k < 8; k++) {
        int idx = tid + k * 256;               // 2048 = 32 rows x 64 rules
        int m   = idx >> 6;
        int rr  = idx & 63;
        float f = es[m * 65 + rr] / ssum[m];
        if (f != 0.0f) {
            int pos = atomicAdd(&g_count[rr], 1);
            g_lb[rr][pos] = row0 + m;
            g_lf[rr][pos] = f;
        }
    }
}

// ---------------------------------------------------------------------------
// Build worklist: one descriptor per (rule, chunk, o-half).
// desc = (r << 11) | (chunk << 1) | half
// ---------------------------------------------------------------------------
__global__ void builder_kernel()
{
    const int r   = threadIdx.x;               // 64 threads
    const int cnt = g_count[r];
    const int nch = (cnt + MCH - 1) / MCH;
    if (nch == 0) return;
    int base = atomicAdd(&g_nwork, nch * 2);
    for (int j = 0; j < nch; j++) {
        g_work[base + 2 * j]     = (r << 11) | (j << 1);
        g_work[base + 2 * j + 1] = (r << 11) | (j << 1) | 1;
    }
}

// ---------------------------------------------------------------------------
// Persistent expert blocks pop work items. Item = 16 rows x 128 o-columns of
// one rule. Thread = one o column; W prefetched IUNR-deep; x tile transposed
// in SMEM so the 16 row-values per i come from 4 broadcast LDS.128.
// ---------------------------------------------------------------------------
__global__ __launch_bounds__(128) void expert_kernel(
    const float* __restrict__ x,
    const float* __restrict__ W,
    const float* __restrict__ bias,
    float* __restrict__ out)
{
    __shared__ float xst[D_SZ * XPAD];         // 20 KB
    __shared__ int   sb[MCH];
    __shared__ float sf[MCH];
    __shared__ int   s_cur;

    const int tid   = threadIdx.x;
    const int nwork = g_nwork;

    while (true) {
        __syncthreads();                       // protect s_cur + smem reuse
        if (tid == 0) s_cur = atomicAdd(&g_fetch, 1);
        __syncthreads();
        const int cur = s_cur;
        if (cur >= nwork) return;

        const int desc = g_work[cur];
        const int r    = desc >> 11;
        const int half = desc & 1;
        const int c0   = ((desc >> 1) & 1023) * MCH;
        const int cnt  = g_count[r];

        if (tid < MCH) {
            int p = c0 + tid;
            int bb = 0; float ff = 0.0f;
            if (p < cnt) { bb = g_lb[r][p]; ff = g_lf[r][p]; }
            sb[tid] = bb; sf[tid] = ff;
        }
        __syncthreads();

        // Stage 16 x rows transposed: thread owns i = tid and i = tid+128.
        #pragma unroll
        for (int m = 0; m < MCH; m++) {
            const float* xr = x + (size_t)sb[m] * D_SZ;
            xst[tid * XPAD + m]         = xr[tid];
            xst[(tid + 128) * XPAD + m] = xr[tid + 128];
        }
        __syncthreads();

        const int    o  = half * 128 + tid;
        const float* Wp = W + ((size_t)r << 16) + o;
        const float  bv = bias[(r << 8) + o];

        float acc[MCH];
        #pragma unroll
        for (int m = 0; m < MCH; m++) acc[m] = 0.0f;

        float w[IUNR];
        #pragma unroll
        for (int k = 0; k < IUNR; k++) w[k] = Wp[k << 8];

        for (int i0 = 0; i0 < D_SZ; i0 += IUNR) {
            float wn[IUNR];
            const bool more = (i0 + IUNR) < D_SZ;
            #pragma unroll
            for (int k = 0; k < IUNR; k++)
                if (more) wn[k] = Wp[(i0 + IUNR + k) << 8];

            #pragma unroll
            for (int k = 0; k < IUNR; k++) {
                const float4* xp = (const float4*)&xst[(i0 + k) * XPAD];
                const float4 x0 = xp[0], x1 = xp[1], x2 = xp[2], x3 = xp[3];
                const float wk = w[k];
                acc[0]  = fmaf(wk, x0.x, acc[0]);
                acc[1]  = fmaf(wk, x0.y, acc[1]);
                acc[2]  = fmaf(wk, x0.z, acc[2]);
                acc[3]  = fmaf(wk, x0.w, acc[3]);
                acc[4]  = fmaf(wk, x1.x, acc[4]);
                acc[5]  = fmaf(wk, x1.y, acc[5]);
                acc[6]  = fmaf(wk, x1.z, acc[6]);
                acc[7]  = fmaf(wk, x1.w, acc[7]);
                acc[8]  = fmaf(wk, x2.x, acc[8]);
                acc[9]  = fmaf(wk, x2.y, acc[9]);
                acc[10] = fmaf(wk, x2.z, acc[10]);
                acc[11] = fmaf(wk, x2.w, acc[11]);
                acc[12] = fmaf(wk, x3.x, acc[12]);
                acc[13] = fmaf(wk, x3.y, acc[13]);
                acc[14] = fmaf(wk, x3.z, acc[14]);
                acc[15] = fmaf(wk, x3.w, acc[15]);
            }
            #pragma unroll
            for (int k = 0; k < IUNR; k++) w[k] = wn[k];
        }

        #pragma unroll
        for (int m = 0; m < MCH; m++) {
            const float f = sf[m];
            if (f != 0.0f)
                atomicAdd(&out[((size_t)sb[m] << 8) + o], f * (acc[m] + bv));
        }
    }
}

// ---------------------------------------------------------------------------
extern "C" void kernel_launch(void* const* d_in, const int* in_sizes, int n_in,
                              void* d_out, int out_size)
{
    const float* x   = (const float*)d_in[0];   // [8192, 256]
    const float* mu  = (const float*)d_in[1];   // [256, 64]
    const float* sig = (const float*)d_in[2];   // [256, 64]
    const float* W   = (const float*)d_in[3];   // [64, 256, 256]
    const float* b   = (const float*)d_in[4];   // [64, 256]
    float* out       = (float*)d_out;           // [8192, 256]

    reset_kernel<<<512, 256>>>((float4*)out);
    prep_kernel<<<R_SZ, 256>>>(mu, sig);
    memb_kernel<<<B_SZ / MROWS, 256>>>(x);
    builder_kernel<<<1, R_SZ>>>();
    expert_kernel<<<EGRID, 128>>>(x, W, b, out);
}